// round 15
// baseline (speedup 1.0000x reference)
#include <cuda_runtime.h>
#include <math.h>

// Shapes (fixed by problem)
#define B_    256
#define L_    32
#define H_    512
#define NROWS (B_ * L_)      // 8192 slots
#define NCOMP (5 * H_)       // 2560

// ---------------- persistent device state (device-code access ONLY) ------
__device__ float g_h [NROWS * H_];
__device__ float g_c [NROWS * H_];
__device__ float g_nh[NROWS * H_];
__device__ float g_nc[NROWS * H_];
__device__ float g_pl[NROWS * NCOMP];
__device__ float g_pr[NROWS * NCOMP];
__device__ float g_logit[NROWS];
__device__ int   g_idx[B_ * L_];
__device__ int   g_et[NROWS];            // initial element-task list (compacted)
__device__ int4  g_pt[NROWS];            // initial pair-task list (compacted)
__device__ int   g_ec[2];
__device__ int   g_pc[2];
__device__ int   g_perm[B_];             // batches sorted by length desc (stable)
__device__ int   g_nact[32];             // #batches merging at step i
__device__ int   g_emerge[B_];           // per-batch merged slot this step (-1 none)
__device__ int   g_ptn[B_];              // per-batch pair-task count (<=2)
__device__ int4  g_ptask[B_ * 2];        // per-batch pair tasks

__device__ __forceinline__ float sigmf(float x) { return 1.f / (1.f + expf(-x)); }

// ---------------- init ----------------
__global__ void k_zero() {
    if (threadIdx.x < 2) { g_ec[threadIdx.x] = 0; g_pc[threadIdx.x] = 0; }
}

__global__ void k_init(const int* __restrict__ length) {
    int b = blockIdx.x;
    g_idx[b * 32 + threadIdx.x] = threadIdx.x;
    if (threadIdx.x == 0) {
        int len = length[b];
        int be = atomicAdd(&g_ec[0], len);
        for (int e = 0; e < len; e++) g_et[be + e] = b * 32 + e;
        int bp = atomicAdd(&g_pc[0], len - 1);
        for (int k = 0; k < len - 1; k++) g_pt[bp + k] = make_int4(b, k, k + 1, k);
    }
}

// length-sorted permutation + per-step active count
__global__ void k_init2(const int* __restrict__ length) {
    __shared__ int slen[B_];
    int t = threadIdx.x;
    slen[t] = length[t];
    __syncthreads();
    int myl = slen[t];
    int rank = 0;
    for (int j = 0; j < B_; j++) {
        int lj = slen[j];
        if (lj > myl || (lj == myl && j < t)) rank++;
    }
    g_perm[rank] = t;
    if (t < 31) {            // batch merges at step i iff len >= i+2
        int cnt = 0;
        for (int j = 0; j < B_; j++) if (slen[j] >= t + 2) cnt++;
        g_nact[t] = cnt;
    }
}

// ---------------- initial gather GEMMs, dbuf, 4x8 tile (split-N frag) ----
// MODE 0 (word proj): A = X[et], B = Ww (N=1024), +bw -> g_h|g_c
// MODE 1 (fill partials): A = g_h[et], B = Wc halves (N=5120) -> g_pl|g_pr
template<int MODE>
__global__ __launch_bounds__(256, 3)
void k_ggemm(const float* __restrict__ X,
             const float* __restrict__ W,
             const float* __restrict__ bias)
{
    constexpr int BM = 128, BN = 64, BK = 16;
    int nt = g_ec[0];
    int mbase = blockIdx.y * BM;
    if (mbase >= nt) return;
    int nbase = blockIdx.x * BN;
    __shared__ float As[2][BK][BM + 4];
    __shared__ float Bs[2][BK][BN + 4];
    int tid = threadIdx.x;
    int tx = tid & 7, ty = tid >> 3;          // 8 x 32 thread grid, 4 rows x (4+4 split cols)
    float acc[4][8];
#pragma unroll
    for (int i = 0; i < 4; i++)
#pragma unroll
        for (int j = 0; j < 8; j++) acc[i][j] = 0.f;

    const float* Abase = (MODE == 0) ? X : g_h;
    const float* aptr[2];
    int ar[2], ak[2];
    bool av[2];
#pragma unroll
    for (int l = 0; l < 2; l++) {
        int fa = tid + l * 256;
        ar[l] = fa >> 2; ak[l] = (fa & 3) * 4;
        int m = mbase + ar[l];
        av[l] = (m < nt);
        aptr[l] = av[l] ? (Abase + (size_t)g_et[m] * 512) : Abase;
    }
    int br = tid >> 2, bk = (tid & 3) * 4;
    int nb = nbase + br;
    const float* wp;
    if (MODE == 0) wp = W + (size_t)nb * 512;
    else           wp = (nb < NCOMP) ? (W + (size_t)nb * 1024)
                                     : (W + (size_t)(nb - NCOMP) * 1024 + 512);

    float4 pa0, pa1, pb;
    pa0 = av[0] ? *(const float4*)(aptr[0] + ak[0]) : make_float4(0.f,0.f,0.f,0.f);
    pa1 = av[1] ? *(const float4*)(aptr[1] + ak[1]) : make_float4(0.f,0.f,0.f,0.f);
    pb  = *(const float4*)(wp + bk);
    As[0][ak[0] + 0][ar[0]] = pa0.x; As[0][ak[0] + 1][ar[0]] = pa0.y;
    As[0][ak[0] + 2][ar[0]] = pa0.z; As[0][ak[0] + 3][ar[0]] = pa0.w;
    As[0][ak[1] + 0][ar[1]] = pa1.x; As[0][ak[1] + 1][ar[1]] = pa1.y;
    As[0][ak[1] + 2][ar[1]] = pa1.z; As[0][ak[1] + 3][ar[1]] = pa1.w;
    Bs[0][bk + 0][br] = pb.x; Bs[0][bk + 1][br] = pb.y;
    Bs[0][bk + 2][br] = pb.z; Bs[0][bk + 3][br] = pb.w;
    __syncthreads();

    constexpr int NIT = 512 / BK;
    for (int it = 0; it < NIT; it++) {
        int cur = it & 1;
        if (it + 1 < NIT) {            // prefetch next chunk into regs
            int kt = (it + 1) * BK;
            pa0 = av[0] ? *(const float4*)(aptr[0] + kt + ak[0]) : make_float4(0.f,0.f,0.f,0.f);
            pa1 = av[1] ? *(const float4*)(aptr[1] + kt + ak[1]) : make_float4(0.f,0.f,0.f,0.f);
            pb  = *(const float4*)(wp + kt + bk);
        }
#pragma unroll
        for (int kk = 0; kk < BK; kk++) {
            float a[4], bb[8];
            {
                float4 t0 = *(const float4*)&As[cur][kk][ty * 4];
                a[0] = t0.x; a[1] = t0.y; a[2] = t0.z; a[3] = t0.w;
            }
            {   // split-N: two conflict-free float4s at tx*4 and tx*4+32
                float4 u0 = *(const float4*)&Bs[cur][kk][tx * 4];
                float4 u1 = *(const float4*)&Bs[cur][kk][tx * 4 + 32];
                bb[0] = u0.x; bb[1] = u0.y; bb[2] = u0.z; bb[3] = u0.w;
                bb[4] = u1.x; bb[5] = u1.y; bb[6] = u1.z; bb[7] = u1.w;
            }
#pragma unroll
            for (int im = 0; im < 4; im++)
#pragma unroll
                for (int in = 0; in < 8; in++) acc[im][in] += a[im] * bb[in];
        }
        if (it + 1 < NIT) {
            int nxt = 1 - cur;
            As[nxt][ak[0] + 0][ar[0]] = pa0.x; As[nxt][ak[0] + 1][ar[0]] = pa0.y;
            As[nxt][ak[0] + 2][ar[0]] = pa0.z; As[nxt][ak[0] + 3][ar[0]] = pa0.w;
            As[nxt][ak[1] + 0][ar[1]] = pa1.x; As[nxt][ak[1] + 1][ar[1]] = pa1.y;
            As[nxt][ak[1] + 2][ar[1]] = pa1.z; As[nxt][ak[1] + 3][ar[1]] = pa1.w;
            Bs[nxt][bk + 0][br] = pb.x; Bs[nxt][bk + 1][br] = pb.y;
            Bs[nxt][bk + 2][br] = pb.z; Bs[nxt][bk + 3][br] = pb.w;
            __syncthreads();
        }
    }
#pragma unroll
    for (int im = 0; im < 4; im++) {
        int m = mbase + ty * 4 + im;
        if (m < nt) {
            int s = g_et[m];
#pragma unroll
            for (int in = 0; in < 8; in++) {
                int nn = nbase + tx * 4 + ((in < 4) ? in : (32 + in - 4));
                if (MODE == 0) {
                    float val = acc[im][in] + bias[nn];
                    if (nn < 512) g_h[(size_t)s * 512 + nn] = val;
                    else          g_c[(size_t)s * 512 + nn - 512] = val;
                } else {
                    float val = acc[im][in];
                    if (nn < NCOMP) g_pl[(size_t)s * NCOMP + nn] = val;
                    else            g_pr[(size_t)s * NCOMP + nn - NCOMP] = val;
                }
            }
        }
    }
}

// ---------------- step GEMM: partials of merged elements -----------------
// rows 0..nact-1 (length-sorted prefix); BM=32, BN=32, 64 thr, 4x4/thread
// Fine tiles -> many blocks/SM at avg nact: kills wave quantization.
__global__ __launch_bounds__(64)
void k_sgemm(const float* __restrict__ W, int step) {
    constexpr int BK = 16;
    int nt = g_nact[step];
    int mbase = blockIdx.y * 32;
    if (mbase >= nt) return;
    int nbase = blockIdx.x * 32;
    __shared__ float As[2][BK][32 + 4];
    __shared__ float Bs[2][BK][32 + 4];
    int tid = threadIdx.x;
    int tx = tid & 7, ty = tid >> 3;          // 8 x 8 threads, 4x4 tile each

    // A loads: 2 float4/thread (32 rows x 16 K = 512 floats = 128 float4)
    const float* aptr[2];
    int ar[2], ak[2];
    bool av[2];
#pragma unroll
    for (int l = 0; l < 2; l++) {
        int fa = tid + l * 64;
        ar[l] = fa >> 2; ak[l] = (fa & 3) * 4;
        int m = mbase + ar[l];
        av[l] = (m < nt);
        aptr[l] = av[l] ? (g_h + (size_t)g_emerge[g_perm[m]] * 512) : g_h;
    }
    // B loads: 2 float4/thread
    int brr[2], bkk[2];
    const float* wp[2];
#pragma unroll
    for (int l = 0; l < 2; l++) {
        int fb = tid + l * 64;
        brr[l] = fb >> 2; bkk[l] = (fb & 3) * 4;
        int nb = nbase + brr[l];
        wp[l] = (nb < NCOMP) ? (W + (size_t)nb * 1024)
                             : (W + (size_t)(nb - NCOMP) * 1024 + 512);
    }
    float acc[4][4];
#pragma unroll
    for (int i = 0; i < 4; i++)
#pragma unroll
        for (int j = 0; j < 4; j++) acc[i][j] = 0.f;

    float4 pa0, pa1, pb0, pb1;
    pa0 = av[0] ? *(const float4*)(aptr[0] + ak[0]) : make_float4(0.f,0.f,0.f,0.f);
    pa1 = av[1] ? *(const float4*)(aptr[1] + ak[1]) : make_float4(0.f,0.f,0.f,0.f);
    pb0 = *(const float4*)(wp[0] + bkk[0]);
    pb1 = *(const float4*)(wp[1] + bkk[1]);
    As[0][ak[0] + 0][ar[0]] = pa0.x; As[0][ak[0] + 1][ar[0]] = pa0.y;
    As[0][ak[0] + 2][ar[0]] = pa0.z; As[0][ak[0] + 3][ar[0]] = pa0.w;
    As[0][ak[1] + 0][ar[1]] = pa1.x; As[0][ak[1] + 1][ar[1]] = pa1.y;
    As[0][ak[1] + 2][ar[1]] = pa1.z; As[0][ak[1] + 3][ar[1]] = pa1.w;
    Bs[0][bkk[0] + 0][brr[0]] = pb0.x; Bs[0][bkk[0] + 1][brr[0]] = pb0.y;
    Bs[0][bkk[0] + 2][brr[0]] = pb0.z; Bs[0][bkk[0] + 3][brr[0]] = pb0.w;
    Bs[0][bkk[1] + 0][brr[1]] = pb1.x; Bs[0][bkk[1] + 1][brr[1]] = pb1.y;
    Bs[0][bkk[1] + 2][brr[1]] = pb1.z; Bs[0][bkk[1] + 3][brr[1]] = pb1.w;
    __syncthreads();

    constexpr int NIT = 512 / BK;
    for (int it = 0; it < NIT; it++) {
        int cur = it & 1;
        if (it + 1 < NIT) {
            int kt = (it + 1) * BK;
            pa0 = av[0] ? *(const float4*)(aptr[0] + kt + ak[0]) : make_float4(0.f,0.f,0.f,0.f);
            pa1 = av[1] ? *(const float4*)(aptr[1] + kt + ak[1]) : make_float4(0.f,0.f,0.f,0.f);
            pb0 = *(const float4*)(wp[0] + kt + bkk[0]);
            pb1 = *(const float4*)(wp[1] + kt + bkk[1]);
        }
#pragma unroll
        for (int kk = 0; kk < BK; kk++) {
            float a[4], bb[4];
            {   // A broadcast within each 8-thread group (ty shared)
                float4 t0 = *(const float4*)&As[cur][kk][ty * 4];
                a[0] = t0.x; a[1] = t0.y; a[2] = t0.z; a[3] = t0.w;
            }
            {   // B: tx*4 -> banks 0..31 across 8 threads, conflict-free
                float4 t1 = *(const float4*)&Bs[cur][kk][tx * 4];
                bb[0] = t1.x; bb[1] = t1.y; bb[2] = t1.z; bb[3] = t1.w;
            }
#pragma unroll
            for (int im = 0; im < 4; im++)
#pragma unroll
                for (int in = 0; in < 4; in++) acc[im][in] += a[im] * bb[in];
        }
        if (it + 1 < NIT) {
            int nxt = 1 - cur;
            As[nxt][ak[0] + 0][ar[0]] = pa0.x; As[nxt][ak[0] + 1][ar[0]] = pa0.y;
            As[nxt][ak[0] + 2][ar[0]] = pa0.z; As[nxt][ak[0] + 3][ar[0]] = pa0.w;
            As[nxt][ak[1] + 0][ar[1]] = pa1.x; As[nxt][ak[1] + 1][ar[1]] = pa1.y;
            As[nxt][ak[1] + 2][ar[1]] = pa1.z; As[nxt][ak[1] + 3][ar[1]] = pa1.w;
            Bs[nxt][bkk[0] + 0][brr[0]] = pb0.x; Bs[nxt][bkk[0] + 1][brr[0]] = pb0.y;
            Bs[nxt][bkk[0] + 2][brr[0]] = pb0.z; Bs[nxt][bkk[0] + 3][brr[0]] = pb0.w;
            Bs[nxt][bkk[1] + 0][brr[1]] = pb1.x; Bs[nxt][bkk[1] + 1][brr[1]] = pb1.y;
            Bs[nxt][bkk[1] + 2][brr[1]] = pb1.z; Bs[nxt][bkk[1] + 3][brr[1]] = pb1.w;
            __syncthreads();
        }
    }
#pragma unroll
    for (int im = 0; im < 4; im++) {
        int mm = mbase + ty * 4 + im;
        if (mm < nt) {
            int slot = g_emerge[g_perm[mm]];
#pragma unroll
            for (int in = 0; in < 4; in++) {
                int nn = nbase + tx * 4 + in;
                if (nn < NCOMP) g_pl[(size_t)slot * NCOMP + nn] = acc[im][in];
                else            g_pr[(size_t)slot * NCOMP + nn - NCOMP] = acc[im][in];
            }
        }
    }
}

// ---------------- initial pair elementwise: 2 pairs / 256-thr block ------
__global__ void k_ew(const float* __restrict__ bc, const float* __restrict__ q) {
    int tid = threadIdx.x;
    int sub = tid >> 7, e = tid & 127;
    int t = blockIdx.x * 2 + sub;
    __shared__ float red[2][4];
    bool valid = (t < g_pc[0]);
    float accq = 0.f;
    int bdst = 0;
    if (valid) {
        int4 tk = g_pt[t];
        int b = tk.x, sl = tk.y, sr = tk.z, dst = tk.w;
        bdst = b * 32 + dst;
        const float4* pl  = (const float4*)(g_pl + (size_t)(b * 32 + sl) * NCOMP);
        const float4* pr  = (const float4*)(g_pr + (size_t)(b * 32 + sr) * NCOMP);
        const float4* bc4 = (const float4*)bc;
        const float4* cl4 = (const float4*)(g_c + (size_t)(b * 32 + sl) * H_);
        const float4* cr4 = (const float4*)(g_c + (size_t)(b * 32 + sr) * H_);
        float4* nh4 = (float4*)(g_nh + (size_t)bdst * H_);
        float4* nc4 = (float4*)(g_nc + (size_t)bdst * H_);
        const float4* q4 = (const float4*)q;

        float4 vi, vfl, vfr, vu, vo;
#define G(dst_, g_) { float4 a = pl[(g_)*128 + e]; float4 bq = pr[(g_)*128 + e]; float4 c = bc4[(g_)*128 + e]; \
    dst_.x = a.x + bq.x + c.x; dst_.y = a.y + bq.y + c.y; dst_.z = a.z + bq.z + c.z; dst_.w = a.w + bq.w + c.w; }
        G(vi, 0) G(vfl, 1) G(vfr, 2) G(vu, 3) G(vo, 4)
#undef G
        float4 cl = cl4[e], cr = cr4[e];
        float4 cn, hn;
#define C1(m) cn.m = cl.m * sigmf(vfl.m + 1.f) + cr.m * sigmf(vfr.m + 1.f) + tanhf(vu.m) * sigmf(vi.m); \
              hn.m = sigmf(vo.m) * tanhf(cn.m);
        C1(x) C1(y) C1(z) C1(w)
#undef C1
        nh4[e] = hn; nc4[e] = cn;
        float4 qv = q4[e];
        accq = qv.x * hn.x + qv.y * hn.y + qv.z * hn.z + qv.w * hn.w;
    }
    for (int o = 16; o > 0; o >>= 1) accq += __shfl_down_sync(0xffffffffu, accq, o);
    if ((tid & 31) == 0) red[sub][(tid >> 5) & 3] = accq;
    __syncthreads();
    if (valid && e == 0) {
        float s = red[sub][0] + red[sub][1] + red[sub][2] + red[sub][3];
        g_logit[bdst] = s * 0.04419417382415922f;
    }
}

// ---------------- fused: ew(step-1 tasks) + select(step) + commit --------
__global__ void k_fused(const int* __restrict__ length,
                        const float* __restrict__ bc, const float* __restrict__ q,
                        int step) {
    int b = blockIdx.x, tid = threadIdx.x;
    __shared__ float redc[2][4];
    __shared__ int s_sl;

    if (step > 0) {
        int ntask = g_ptn[b];
        int sub = tid >> 7, lt = tid & 127;
        int wig = (tid >> 5) & 3;
        bool valid = (sub < ntask);
        float accq = 0.f;
        int bdst = 0;
        if (valid) {
            int4 tk = g_ptask[b * 2 + sub];
            int sl = tk.y, sr = tk.z, dst = tk.w;
            bdst = b * 32 + dst;
            const float4* pl  = (const float4*)(g_pl + (size_t)(b * 32 + sl) * NCOMP);
            const float4* pr  = (const float4*)(g_pr + (size_t)(b * 32 + sr) * NCOMP);
            const float4* bc4 = (const float4*)bc;
            const float4* cl4 = (const float4*)(g_c + (size_t)(b * 32 + sl) * H_);
            const float4* cr4 = (const float4*)(g_c + (size_t)(b * 32 + sr) * H_);
            float4* nh4 = (float4*)(g_nh + (size_t)bdst * H_);
            float4* nc4 = (float4*)(g_nc + (size_t)bdst * H_);
            const float4* q4 = (const float4*)q;
            float4 vi, vfl, vfr, vu, vo;
#define G(dst_, g_) { float4 a = pl[(g_)*128 + lt]; float4 bq = pr[(g_)*128 + lt]; float4 c = bc4[(g_)*128 + lt]; \
    dst_.x = a.x + bq.x + c.x; dst_.y = a.y + bq.y + c.y; dst_.z = a.z + bq.z + c.z; dst_.w = a.w + bq.w + c.w; }
            G(vi, 0) G(vfl, 1) G(vfr, 2) G(vu, 3) G(vo, 4)
#undef G
            float4 cl = cl4[lt], cr = cr4[lt];
            float4 cn, hn;
#define C1(m) cn.m = cl.m * sigmf(vfl.m + 1.f) + cr.m * sigmf(vfr.m + 1.f) + tanhf(vu.m) * sigmf(vi.m); \
              hn.m = sigmf(vo.m) * tanhf(cn.m);
            C1(x) C1(y) C1(z) C1(w)
#undef C1
            nh4[lt] = hn; nc4[lt] = cn;
            float4 qv = q4[lt];
            accq = qv.x * hn.x + qv.y * hn.y + qv.z * hn.z + qv.w * hn.w;
        }
        for (int o = 16; o > 0; o >>= 1) accq += __shfl_down_sync(0xffffffffu, accq, o);
        if ((tid & 31) == 0) redc[sub][wig] = accq;
        __syncthreads();
        if (valid && lt == 0) {
            float s = redc[sub][0] + redc[sub][1] + redc[sub][2] + redc[sub][3];
            g_logit[bdst] = s * 0.04419417382415922f;
        }
        __syncthreads();
    }

    // select: parallel warp argmax (first-max tie-break == jnp.argmax)
    if (tid < 32) {
        int len = length[b];
        int vc = len - step - 1;
        int sl = -1, nt2 = 0;
        int* ip = g_idx + b * 32;
        if (vc >= 1) {
            float val = -3.0e38f;
            int ki = tid;
            if (tid < vc) val = g_logit[b * 32 + ip[tid]];
            for (int o = 16; o > 0; o >>= 1) {
                float ov = __shfl_down_sync(0xffffffffu, val, o);
                int   ok = __shfl_down_sync(0xffffffffu, ki, o);
                if (ov > val || (ov == val && ok < ki)) { val = ov; ki = ok; }
            }
            int jb = __shfl_sync(0xffffffffu, ki, 0);
            if (tid == 0) {
                sl = ip[jb];
                if (step < 30) {
                    if (jb >= 1)      g_ptask[b * 2 + nt2++] = make_int4(b, ip[jb - 1], sl, ip[jb - 1]);
                    if (jb <= vc - 2) g_ptask[b * 2 + nt2++] = make_int4(b, sl, ip[jb + 2], sl);
                }
                int n = 32 - step;
                for (int k2 = jb + 1; k2 < n - 1; k2++) ip[k2] = ip[k2 + 1];
            }
        }
        if (tid == 0) {
            g_ptn[b] = nt2;
            g_emerge[b] = (sl >= 0 && step < 30) ? (b * 32 + sl) : -1;
            s_sl = sl;
        }
    }
    __syncthreads();
    int sl = s_sl;
    if (sl >= 0) {   // commit merge: cached compose -> live h/c
        size_t ro = (size_t)(b * 32 + sl) * H_;
        int e = tid & 127;
        if (tid < 128) ((float4*)(g_h + ro))[e] = ((const float4*)(g_nh + ro))[e];
        else           ((float4*)(g_c + ro))[e] = ((const float4*)(g_nc + ro))[e];
    }
}

__global__ void k_final(float* __restrict__ out) {
    int b = blockIdx.x;   // element 0 lives in slot 0 forever
    ((float4*)out)[b * 128 + threadIdx.x] =
        ((const float4*)(g_h + (size_t)b * 32 * H_))[threadIdx.x];
}

// ---------------- launch ----------------
extern "C" void kernel_launch(void* const* d_in, const int* in_sizes, int n_in,
                              void* d_out, int out_size) {
    const float* x      = (const float*)d_in[0];
    const int*   length = (const int*)  d_in[1];
    const float* Ww     = (const float*)d_in[2];
    const float* bw     = (const float*)d_in[3];
    const float* Wc     = (const float*)d_in[4];
    const float* bc     = (const float*)d_in[5];
    const float* q      = (const float*)d_in[6];
    float* out = (float*)d_out;

    k_zero<<<1, 32>>>();
    k_init<<<B_, 32>>>(length);
    k_init2<<<1, 256>>>(length);

    // word projection (gathered, valid elements only): h|c = x @ Ww^T + bw
    k_ggemm<0><<<dim3(1024 / 64, 64), 256>>>(x, Ww, bw);
    // initial partial fill: pl|pr = Wl@h | Wr@h for all valid elements
    k_ggemm<1><<<dim3(5120 / 64, 64), 256>>>((const float*)0, Wc, (const float*)0);
    // initial pair cache (adds + activations + logits), 2 pairs per block
    k_ew<<<4096, 256>>>(bc, q);

    for (int i = 0; i < 31; i++) {
        k_fused<<<B_, 256>>>(length, bc, q, i);
        if (i < 30)
            k_sgemm<<<dim3(5120 / 32, 8), 64>>>(Wc, i);
    }
    k_final<<<B_, 128>>>(out);
}

// round 16
// speedup vs baseline: 1.0177x; 1.0177x over previous
#include <cuda_runtime.h>
#include <math.h>

// Shapes (fixed by problem)
#define B_    256
#define L_    32
#define H_    512
#define NROWS (B_ * L_)      // 8192 slots
#define NCOMP (5 * H_)       // 2560

// ---------------- persistent device state (device-code access ONLY) ------
__device__ float g_h [NROWS * H_];
__device__ float g_c [NROWS * H_];
__device__ float g_nh[NROWS * H_];
__device__ float g_nc[NROWS * H_];
__device__ float g_pl[NROWS * NCOMP];
__device__ float g_pr[NROWS * NCOMP];
__device__ float g_logit[NROWS];
__device__ int   g_idx[B_ * L_];
__device__ int   g_et[NROWS];            // initial element-task list (compacted)
__device__ int4  g_pt[NROWS];            // initial pair-task list (compacted)
__device__ int   g_ec[2];
__device__ int   g_pc[2];
__device__ int   g_perm[B_];             // batches sorted by length desc (stable)
__device__ int   g_nact[32];             // #batches merging at step i
__device__ int   g_emerge[B_];           // per-batch merged slot this step (-1 none)
__device__ int   g_ptn[B_];              // per-batch pair-task count (<=2)
__device__ int4  g_ptask[B_ * 2];        // per-batch pair tasks

__device__ __forceinline__ float sigmf(float x) { return 1.f / (1.f + expf(-x)); }

// ---------------- init ----------------
__global__ void k_zero() {
    if (threadIdx.x < 2) { g_ec[threadIdx.x] = 0; g_pc[threadIdx.x] = 0; }
}

__global__ void k_init(const int* __restrict__ length) {
    int b = blockIdx.x;
    g_idx[b * 32 + threadIdx.x] = threadIdx.x;
    if (threadIdx.x == 0) {
        int len = length[b];
        int be = atomicAdd(&g_ec[0], len);
        for (int e = 0; e < len; e++) g_et[be + e] = b * 32 + e;
        int bp = atomicAdd(&g_pc[0], len - 1);
        for (int k = 0; k < len - 1; k++) g_pt[bp + k] = make_int4(b, k, k + 1, k);
    }
}

// length-sorted permutation + per-step active count
__global__ void k_init2(const int* __restrict__ length) {
    __shared__ int slen[B_];
    int t = threadIdx.x;
    slen[t] = length[t];
    __syncthreads();
    int myl = slen[t];
    int rank = 0;
    for (int j = 0; j < B_; j++) {
        int lj = slen[j];
        if (lj > myl || (lj == myl && j < t)) rank++;
    }
    g_perm[rank] = t;
    if (t < 31) {            // batch merges at step i iff len >= i+2
        int cnt = 0;
        for (int j = 0; j < B_; j++) if (slen[j] >= t + 2) cnt++;
        g_nact[t] = cnt;
    }
}

// ---------------- initial gather GEMMs: 128 thr, 8x8/thread, dbuf --------
// Micro-tile split 4+4 in both dims: A frags at ty*4 / ty*4+64 (broadcast),
// B frags at tx*4 / tx*4+32 (banks 0..31 per quarter-warp). 1.0 B smem/MAC.
// MODE 0 (word proj): A = X[et], B = Ww (N=1024), +bw -> g_h|g_c
// MODE 1 (fill partials): A = g_h[et], B = Wc halves (N=5120) -> g_pl|g_pr
template<int MODE>
__global__ __launch_bounds__(128)
void k_ggemm(const float* __restrict__ X,
             const float* __restrict__ W,
             const float* __restrict__ bias)
{
    constexpr int BM = 128, BN = 64, BK = 16;
    int nt = g_ec[0];
    int mbase = blockIdx.y * BM;
    if (mbase >= nt) return;
    int nbase = blockIdx.x * BN;
    __shared__ float As[2][BK][BM + 4];
    __shared__ float Bs[2][BK][BN + 4];
    int tid = threadIdx.x;
    int tx = tid & 7, ty = tid >> 3;          // 8 x 16 thread grid
    float acc[8][8];
#pragma unroll
    for (int i = 0; i < 8; i++)
#pragma unroll
        for (int j = 0; j < 8; j++) acc[i][j] = 0.f;

    const float* Abase = (MODE == 0) ? X : g_h;
    // A loads: 4 float4/thread (128 rows x 16 K = 512 float4)
    const float* aptr[4];
    int ar[4], ak[4];
    bool av[4];
#pragma unroll
    for (int l = 0; l < 4; l++) {
        int fa = tid + l * 128;
        ar[l] = fa >> 2; ak[l] = (fa & 3) * 4;
        int m = mbase + ar[l];
        av[l] = (m < nt);
        aptr[l] = av[l] ? (Abase + (size_t)g_et[m] * 512) : Abase;
    }
    // B loads: 2 float4/thread (64 rows x 16 K = 256 float4)
    int brr[2], bkk[2];
    const float* wp[2];
#pragma unroll
    for (int l = 0; l < 2; l++) {
        int fb = tid + l * 128;
        brr[l] = fb >> 2; bkk[l] = (fb & 3) * 4;
        int nb = nbase + brr[l];
        if (MODE == 0) wp[l] = W + (size_t)nb * 512;
        else           wp[l] = (nb < NCOMP) ? (W + (size_t)nb * 1024)
                                            : (W + (size_t)(nb - NCOMP) * 1024 + 512);
    }

    float4 pa[4], pb[2];
#pragma unroll
    for (int l = 0; l < 4; l++)
        pa[l] = av[l] ? *(const float4*)(aptr[l] + ak[l]) : make_float4(0.f,0.f,0.f,0.f);
#pragma unroll
    for (int l = 0; l < 2; l++)
        pb[l] = *(const float4*)(wp[l] + bkk[l]);
#pragma unroll
    for (int l = 0; l < 4; l++) {
        As[0][ak[l] + 0][ar[l]] = pa[l].x; As[0][ak[l] + 1][ar[l]] = pa[l].y;
        As[0][ak[l] + 2][ar[l]] = pa[l].z; As[0][ak[l] + 3][ar[l]] = pa[l].w;
    }
#pragma unroll
    for (int l = 0; l < 2; l++) {
        Bs[0][bkk[l] + 0][brr[l]] = pb[l].x; Bs[0][bkk[l] + 1][brr[l]] = pb[l].y;
        Bs[0][bkk[l] + 2][brr[l]] = pb[l].z; Bs[0][bkk[l] + 3][brr[l]] = pb[l].w;
    }
    __syncthreads();

    constexpr int NIT = 512 / BK;
    for (int it = 0; it < NIT; it++) {
        int cur = it & 1;
        if (it + 1 < NIT) {            // prefetch next chunk into regs
            int kt = (it + 1) * BK;
#pragma unroll
            for (int l = 0; l < 4; l++)
                pa[l] = av[l] ? *(const float4*)(aptr[l] + kt + ak[l]) : make_float4(0.f,0.f,0.f,0.f);
#pragma unroll
            for (int l = 0; l < 2; l++)
                pb[l] = *(const float4*)(wp[l] + kt + bkk[l]);
        }
#pragma unroll
        for (int kk = 0; kk < BK; kk++) {
            float a[8], bb[8];
            {
                float4 t0 = *(const float4*)&As[cur][kk][ty * 4];
                float4 t1 = *(const float4*)&As[cur][kk][ty * 4 + 64];
                a[0] = t0.x; a[1] = t0.y; a[2] = t0.z; a[3] = t0.w;
                a[4] = t1.x; a[5] = t1.y; a[6] = t1.z; a[7] = t1.w;
            }
            {
                float4 u0 = *(const float4*)&Bs[cur][kk][tx * 4];
                float4 u1 = *(const float4*)&Bs[cur][kk][tx * 4 + 32];
                bb[0] = u0.x; bb[1] = u0.y; bb[2] = u0.z; bb[3] = u0.w;
                bb[4] = u1.x; bb[5] = u1.y; bb[6] = u1.z; bb[7] = u1.w;
            }
#pragma unroll
            for (int im = 0; im < 8; im++)
#pragma unroll
                for (int in = 0; in < 8; in++) acc[im][in] += a[im] * bb[in];
        }
        if (it + 1 < NIT) {
            int nxt = 1 - cur;
#pragma unroll
            for (int l = 0; l < 4; l++) {
                As[nxt][ak[l] + 0][ar[l]] = pa[l].x; As[nxt][ak[l] + 1][ar[l]] = pa[l].y;
                As[nxt][ak[l] + 2][ar[l]] = pa[l].z; As[nxt][ak[l] + 3][ar[l]] = pa[l].w;
            }
#pragma unroll
            for (int l = 0; l < 2; l++) {
                Bs[nxt][bkk[l] + 0][brr[l]] = pb[l].x; Bs[nxt][bkk[l] + 1][brr[l]] = pb[l].y;
                Bs[nxt][bkk[l] + 2][brr[l]] = pb[l].z; Bs[nxt][bkk[l] + 3][brr[l]] = pb[l].w;
            }
            __syncthreads();
        }
    }
#pragma unroll
    for (int im = 0; im < 8; im++) {
        int m = mbase + ((im < 4) ? (ty * 4 + im) : (64 + ty * 4 + im - 4));
        if (m < nt) {
            int s = g_et[m];
#pragma unroll
            for (int in = 0; in < 8; in++) {
                int nn = nbase + tx * 4 + ((in < 4) ? in : (32 + in - 4));
                if (MODE == 0) {
                    float val = acc[im][in] + bias[nn];
                    if (nn < 512) g_h[(size_t)s * 512 + nn] = val;
                    else          g_c[(size_t)s * 512 + nn - 512] = val;
                } else {
                    float val = acc[im][in];
                    if (nn < NCOMP) g_pl[(size_t)s * NCOMP + nn] = val;
                    else            g_pr[(size_t)s * NCOMP + nn - NCOMP] = val;
                }
            }
        }
    }
}

// ---------------- step GEMM: partials of merged elements -----------------
// rows 0..nact-1 (length-sorted prefix); BM=32, BN=32, 64 thr, 4x4/thread
__global__ __launch_bounds__(64)
void k_sgemm(const float* __restrict__ W, int step) {
    constexpr int BK = 16;
    int nt = g_nact[step];
    int mbase = blockIdx.y * 32;
    if (mbase >= nt) return;
    int nbase = blockIdx.x * 32;
    __shared__ float As[2][BK][32 + 4];
    __shared__ float Bs[2][BK][32 + 4];
    int tid = threadIdx.x;
    int tx = tid & 7, ty = tid >> 3;          // 8 x 8 threads, 4x4 tile each

    const float* aptr[2];
    int ar[2], ak[2];
    bool av[2];
#pragma unroll
    for (int l = 0; l < 2; l++) {
        int fa = tid + l * 64;
        ar[l] = fa >> 2; ak[l] = (fa & 3) * 4;
        int m = mbase + ar[l];
        av[l] = (m < nt);
        aptr[l] = av[l] ? (g_h + (size_t)g_emerge[g_perm[m]] * 512) : g_h;
    }
    int brr[2], bkk[2];
    const float* wp[2];
#pragma unroll
    for (int l = 0; l < 2; l++) {
        int fb = tid + l * 64;
        brr[l] = fb >> 2; bkk[l] = (fb & 3) * 4;
        int nb = nbase + brr[l];
        wp[l] = (nb < NCOMP) ? (W + (size_t)nb * 1024)
                             : (W + (size_t)(nb - NCOMP) * 1024 + 512);
    }
    float acc[4][4];
#pragma unroll
    for (int i = 0; i < 4; i++)
#pragma unroll
        for (int j = 0; j < 4; j++) acc[i][j] = 0.f;

    float4 pa0, pa1, pb0, pb1;
    pa0 = av[0] ? *(const float4*)(aptr[0] + ak[0]) : make_float4(0.f,0.f,0.f,0.f);
    pa1 = av[1] ? *(const float4*)(aptr[1] + ak[1]) : make_float4(0.f,0.f,0.f,0.f);
    pb0 = *(const float4*)(wp[0] + bkk[0]);
    pb1 = *(const float4*)(wp[1] + bkk[1]);
    As[0][ak[0] + 0][ar[0]] = pa0.x; As[0][ak[0] + 1][ar[0]] = pa0.y;
    As[0][ak[0] + 2][ar[0]] = pa0.z; As[0][ak[0] + 3][ar[0]] = pa0.w;
    As[0][ak[1] + 0][ar[1]] = pa1.x; As[0][ak[1] + 1][ar[1]] = pa1.y;
    As[0][ak[1] + 2][ar[1]] = pa1.z; As[0][ak[1] + 3][ar[1]] = pa1.w;
    Bs[0][bkk[0] + 0][brr[0]] = pb0.x; Bs[0][bkk[0] + 1][brr[0]] = pb0.y;
    Bs[0][bkk[0] + 2][brr[0]] = pb0.z; Bs[0][bkk[0] + 3][brr[0]] = pb0.w;
    Bs[0][bkk[1] + 0][brr[1]] = pb1.x; Bs[0][bkk[1] + 1][brr[1]] = pb1.y;
    Bs[0][bkk[1] + 2][brr[1]] = pb1.z; Bs[0][bkk[1] + 3][brr[1]] = pb1.w;
    __syncthreads();

    constexpr int NIT = 512 / BK;
    for (int it = 0; it < NIT; it++) {
        int cur = it & 1;
        if (it + 1 < NIT) {
            int kt = (it + 1) * BK;
            pa0 = av[0] ? *(const float4*)(aptr[0] + kt + ak[0]) : make_float4(0.f,0.f,0.f,0.f);
            pa1 = av[1] ? *(const float4*)(aptr[1] + kt + ak[1]) : make_float4(0.f,0.f,0.f,0.f);
            pb0 = *(const float4*)(wp[0] + kt + bkk[0]);
            pb1 = *(const float4*)(wp[1] + kt + bkk[1]);
        }
#pragma unroll
        for (int kk = 0; kk < BK; kk++) {
            float a[4], bb[4];
            {
                float4 t0 = *(const float4*)&As[cur][kk][ty * 4];
                a[0] = t0.x; a[1] = t0.y; a[2] = t0.z; a[3] = t0.w;
            }
            {
                float4 t1 = *(const float4*)&Bs[cur][kk][tx * 4];
                bb[0] = t1.x; bb[1] = t1.y; bb[2] = t1.z; bb[3] = t1.w;
            }
#pragma unroll
            for (int im = 0; im < 4; im++)
#pragma unroll
                for (int in = 0; in < 4; in++) acc[im][in] += a[im] * bb[in];
        }
        if (it + 1 < NIT) {
            int nxt = 1 - cur;
            As[nxt][ak[0] + 0][ar[0]] = pa0.x; As[nxt][ak[0] + 1][ar[0]] = pa0.y;
            As[nxt][ak[0] + 2][ar[0]] = pa0.z; As[nxt][ak[0] + 3][ar[0]] = pa0.w;
            As[nxt][ak[1] + 0][ar[1]] = pa1.x; As[nxt][ak[1] + 1][ar[1]] = pa1.y;
            As[nxt][ak[1] + 2][ar[1]] = pa1.z; As[nxt][ak[1] + 3][ar[1]] = pa1.w;
            Bs[nxt][bkk[0] + 0][brr[0]] = pb0.x; Bs[nxt][bkk[0] + 1][brr[0]] = pb0.y;
            Bs[nxt][bkk[0] + 2][brr[0]] = pb0.z; Bs[nxt][bkk[0] + 3][brr[0]] = pb0.w;
            Bs[nxt][bkk[1] + 0][brr[1]] = pb1.x; Bs[nxt][bkk[1] + 1][brr[1]] = pb1.y;
            Bs[nxt][bkk[1] + 2][brr[1]] = pb1.z; Bs[nxt][bkk[1] + 3][brr[1]] = pb1.w;
            __syncthreads();
        }
    }
#pragma unroll
    for (int im = 0; im < 4; im++) {
        int mm = mbase + ty * 4 + im;
        if (mm < nt) {
            int slot = g_emerge[g_perm[mm]];
#pragma unroll
            for (int in = 0; in < 4; in++) {
                int nn = nbase + tx * 4 + in;
                if (nn < NCOMP) g_pl[(size_t)slot * NCOMP + nn] = acc[im][in];
                else            g_pr[(size_t)slot * NCOMP + nn - NCOMP] = acc[im][in];
            }
        }
    }
}

// ---------------- initial pair elementwise: 2 pairs / 256-thr block ------
__global__ void k_ew(const float* __restrict__ bc, const float* __restrict__ q) {
    int tid = threadIdx.x;
    int sub = tid >> 7, e = tid & 127;
    int t = blockIdx.x * 2 + sub;
    __shared__ float red[2][4];
    bool valid = (t < g_pc[0]);
    float accq = 0.f;
    int bdst = 0;
    if (valid) {
        int4 tk = g_pt[t];
        int b = tk.x, sl = tk.y, sr = tk.z, dst = tk.w;
        bdst = b * 32 + dst;
        const float4* pl  = (const float4*)(g_pl + (size_t)(b * 32 + sl) * NCOMP);
        const float4* pr  = (const float4*)(g_pr + (size_t)(b * 32 + sr) * NCOMP);
        const float4* bc4 = (const float4*)bc;
        const float4* cl4 = (const float4*)(g_c + (size_t)(b * 32 + sl) * H_);
        const float4* cr4 = (const float4*)(g_c + (size_t)(b * 32 + sr) * H_);
        float4* nh4 = (float4*)(g_nh + (size_t)bdst * H_);
        float4* nc4 = (float4*)(g_nc + (size_t)bdst * H_);
        const float4* q4 = (const float4*)q;

        float4 vi, vfl, vfr, vu, vo;
#define G(dst_, g_) { float4 a = pl[(g_)*128 + e]; float4 bq = pr[(g_)*128 + e]; float4 c = bc4[(g_)*128 + e]; \
    dst_.x = a.x + bq.x + c.x; dst_.y = a.y + bq.y + c.y; dst_.z = a.z + bq.z + c.z; dst_.w = a.w + bq.w + c.w; }
        G(vi, 0) G(vfl, 1) G(vfr, 2) G(vu, 3) G(vo, 4)
#undef G
        float4 cl = cl4[e], cr = cr4[e];
        float4 cn, hn;
#define C1(m) cn.m = cl.m * sigmf(vfl.m + 1.f) + cr.m * sigmf(vfr.m + 1.f) + tanhf(vu.m) * sigmf(vi.m); \
              hn.m = sigmf(vo.m) * tanhf(cn.m);
        C1(x) C1(y) C1(z) C1(w)
#undef C1
        nh4[e] = hn; nc4[e] = cn;
        float4 qv = q4[e];
        accq = qv.x * hn.x + qv.y * hn.y + qv.z * hn.z + qv.w * hn.w;
    }
    for (int o = 16; o > 0; o >>= 1) accq += __shfl_down_sync(0xffffffffu, accq, o);
    if ((tid & 31) == 0) red[sub][(tid >> 5) & 3] = accq;
    __syncthreads();
    if (valid && e == 0) {
        float s = red[sub][0] + red[sub][1] + red[sub][2] + red[sub][3];
        g_logit[bdst] = s * 0.04419417382415922f;
    }
}

// ---------------- fused: ew(step-1 tasks) + select(step) + commit --------
__global__ void k_fused(const int* __restrict__ length,
                        const float* __restrict__ bc, const float* __restrict__ q,
                        int step) {
    int b = blockIdx.x, tid = threadIdx.x;
    __shared__ float redc[2][4];
    __shared__ int s_sl;

    if (step > 0) {
        int ntask = g_ptn[b];
        int sub = tid >> 7, lt = tid & 127;
        int wig = (tid >> 5) & 3;
        bool valid = (sub < ntask);
        float accq = 0.f;
        int bdst = 0;
        if (valid) {
            int4 tk = g_ptask[b * 2 + sub];
            int sl = tk.y, sr = tk.z, dst = tk.w;
            bdst = b * 32 + dst;
            const float4* pl  = (const float4*)(g_pl + (size_t)(b * 32 + sl) * NCOMP);
            const float4* pr  = (const float4*)(g_pr + (size_t)(b * 32 + sr) * NCOMP);
            const float4* bc4 = (const float4*)bc;
            const float4* cl4 = (const float4*)(g_c + (size_t)(b * 32 + sl) * H_);
            const float4* cr4 = (const float4*)(g_c + (size_t)(b * 32 + sr) * H_);
            float4* nh4 = (float4*)(g_nh + (size_t)bdst * H_);
            float4* nc4 = (float4*)(g_nc + (size_t)bdst * H_);
            const float4* q4 = (const float4*)q;
            float4 vi, vfl, vfr, vu, vo;
#define G(dst_, g_) { float4 a = pl[(g_)*128 + lt]; float4 bq = pr[(g_)*128 + lt]; float4 c = bc4[(g_)*128 + lt]; \
    dst_.x = a.x + bq.x + c.x; dst_.y = a.y + bq.y + c.y; dst_.z = a.z + bq.z + c.z; dst_.w = a.w + bq.w + c.w; }
            G(vi, 0) G(vfl, 1) G(vfr, 2) G(vu, 3) G(vo, 4)
#undef G
            float4 cl = cl4[lt], cr = cr4[lt];
            float4 cn, hn;
#define C1(m) cn.m = cl.m * sigmf(vfl.m + 1.f) + cr.m * sigmf(vfr.m + 1.f) + tanhf(vu.m) * sigmf(vi.m); \
              hn.m = sigmf(vo.m) * tanhf(cn.m);
            C1(x) C1(y) C1(z) C1(w)
#undef C1
            nh4[lt] = hn; nc4[lt] = cn;
            float4 qv = q4[lt];
            accq = qv.x * hn.x + qv.y * hn.y + qv.z * hn.z + qv.w * hn.w;
        }
        for (int o = 16; o > 0; o >>= 1) accq += __shfl_down_sync(0xffffffffu, accq, o);
        if ((tid & 31) == 0) redc[sub][wig] = accq;
        __syncthreads();
        if (valid && lt == 0) {
            float s = redc[sub][0] + redc[sub][1] + redc[sub][2] + redc[sub][3];
            g_logit[bdst] = s * 0.04419417382415922f;
        }
        __syncthreads();
    }

    // select: parallel warp argmax (first-max tie-break == jnp.argmax)
    if (tid < 32) {
        int len = length[b];
        int vc = len - step - 1;
        int sl = -1, nt2 = 0;
        int* ip = g_idx + b * 32;
        if (vc >= 1) {
            float val = -3.0e38f;
            int ki = tid;
            if (tid < vc) val = g_logit[b * 32 + ip[tid]];
            for (int o = 16; o > 0; o >>= 1) {
                float ov = __shfl_down_sync(0xffffffffu, val, o);
                int   ok = __shfl_down_sync(0xffffffffu, ki, o);
                if (ov > val || (ov == val && ok < ki)) { val = ov; ki = ok; }
            }
            int jb = __shfl_sync(0xffffffffu, ki, 0);
            if (tid == 0) {
                sl = ip[jb];
                if (step < 30) {
                    if (jb >= 1)      g_ptask[b * 2 + nt2++] = make_int4(b, ip[jb - 1], sl, ip[jb - 1]);
                    if (jb <= vc - 2) g_ptask[b * 2 + nt2++] = make_int4(b, sl, ip[jb + 2], sl);
                }
                int n = 32 - step;
                for (int k2 = jb + 1; k2 < n - 1; k2++) ip[k2] = ip[k2 + 1];
            }
        }
        if (tid == 0) {
            g_ptn[b] = nt2;
            g_emerge[b] = (sl >= 0 && step < 30) ? (b * 32 + sl) : -1;
            s_sl = sl;
        }
    }
    __syncthreads();
    int sl = s_sl;
    if (sl >= 0) {   // commit merge: cached compose -> live h/c
        size_t ro = (size_t)(b * 32 + sl) * H_;
        int e = tid & 127;
        if (tid < 128) ((float4*)(g_h + ro))[e] = ((const float4*)(g_nh + ro))[e];
        else           ((float4*)(g_c + ro))[e] = ((const float4*)(g_nc + ro))[e];
    }
}

__global__ void k_final(float* __restrict__ out) {
    int b = blockIdx.x;   // element 0 lives in slot 0 forever
    ((float4*)out)[b * 128 + threadIdx.x] =
        ((const float4*)(g_h + (size_t)b * 32 * H_))[threadIdx.x];
}

// ---------------- launch ----------------
extern "C" void kernel_launch(void* const* d_in, const int* in_sizes, int n_in,
                              void* d_out, int out_size) {
    const float* x      = (const float*)d_in[0];
    const int*   length = (const int*)  d_in[1];
    const float* Ww     = (const float*)d_in[2];
    const float* bw     = (const float*)d_in[3];
    const float* Wc     = (const float*)d_in[4];
    const float* bc     = (const float*)d_in[5];
    const float* q      = (const float*)d_in[6];
    float* out = (float*)d_out;

    k_zero<<<1, 32>>>();
    k_init<<<B_, 32>>>(length);
    k_init2<<<1, 256>>>(length);

    // word projection (gathered, valid elements only): h|c = x @ Ww^T + bw
    k_ggemm<0><<<dim3(1024 / 64, 64), 128>>>(x, Ww, bw);
    // initial partial fill: pl|pr = Wl@h | Wr@h for all valid elements
    k_ggemm<1><<<dim3(5120 / 64, 64), 128>>>((const float*)0, Wc, (const float*)0);
    // initial pair cache (adds + activations + logits), 2 pairs per block
    k_ew<<<4096, 256>>>(bc, q);

    for (int i = 0; i < 31; i++) {
        k_fused<<<B_, 256>>>(length, bc, q, i);
        if (i < 30)
            k_sgemm<<<dim3(5120 / 32, 8), 64>>>(Wc, i);
    }
    k_final<<<B_, 128>>>(out);
}